// round 13
// baseline (speedup 1.0000x reference)
#include <cuda_runtime.h>
#include <math.h>

#define NV    4096
#define FIN   256
#define HH    128
#define MINC  1024
#define REPC  2
#define XR    6144   // NV + MINC*REPC
#define NCH   3      // j-chunks in fused pass
#define CHJ   (XR/NCH)   // 2048
#define CAP   128    // per-node adjacency capacity (mean deg ~17)

// ---------------- scratch (static __device__, no allocs) ----------------
__device__ __align__(16) float g_p0 [NV*FIN];
__device__ __align__(16) float g_hn0[NV*FIN];
__device__ __align__(16) float g_h  [NV*HH];
__device__ __align__(16) float g_p1 [NV*HH];
__device__ __align__(16) float g_hn1[NV*HH];
__device__ __align__(16) float g_x  [XR*HH];
__device__ __align__(16) float g_xt [HH*XR];          // transposed + tf32-rounded
__device__ __align__(16) float g_out[XR*HH];
__device__ __align__(16) float g_ng4[(size_t)NCH*XR*HH];
__device__ __align__(16) float g_rs4[NCH*XR];
__device__ __align__(16) float g_scal[4];     // 0: edge count, 2: S_non, 3: S_edge
__device__ int g_deg[NV];
__device__ int g_lst[NV*CAP];
__device__ unsigned long long g_nnp[MINC*4];  // packed (d2bits<<32 | j) per j-chunk

__device__ __forceinline__ float tf32r(float x) {
    unsigned u;
    asm("cvt.rna.tf32.f32 %0, %1;" : "=r"(u) : "f"(x));
    return __uint_as_float(u);
}

__device__ __forceinline__ void mma8(float* d, unsigned a0, unsigned a1, unsigned a2,
                                     unsigned a3, unsigned b0, unsigned b1) {
    asm volatile("mma.sync.aligned.m16n8k8.row.col.f32.tf32.tf32.f32 "
                 "{%0,%1,%2,%3}, {%4,%5,%6,%7}, {%8,%9}, {%0,%1,%2,%3};"
                 : "+f"(d[0]), "+f"(d[1]), "+f"(d[2]), "+f"(d[3])
                 : "r"(a0), "r"(a1), "r"(a2), "r"(a3), "r"(b0), "r"(b1));
}

__device__ __forceinline__ void cpa16(unsigned s, const void* g) {
    asm volatile("cp.async.cg.shared.global [%0], [%1], 16;" :: "r"(s), "l"(g));
}
__device__ __forceinline__ void cpa_commit_wait() {
    asm volatile("cp.async.commit_group;");
    asm volatile("cp.async.wait_group 0;" ::: "memory");
}

// ---------------- init ------------------------------------------------------
__global__ void k_init() {
    int i = blockIdx.x*blockDim.x + threadIdx.x;
    if (i < NV) g_deg[i] = 0;
    if (i == 0) { g_scal[0] = 0.f; g_scal[2] = 0.f; g_scal[3] = 0.f; }
}

// ---------------- CSR-ish build: per-dst source lists -----------------------
__global__ void k_build(const int* __restrict__ src, const int* __restrict__ dst, int E) {
    int e = blockIdx.x*blockDim.x + threadIdx.x;
    if (e >= E) return;
    int d = dst[e];
    int slot = atomicAdd(&g_deg[d], 1);
    if (slot < CAP) g_lst[d*CAP + slot] = src[e];
}

// ---------------- gather segment-max, float4-wide, 4x unrolled ---------------
__global__ void k_gmax4(const float* __restrict__ p, float* __restrict__ hn, int F) {
    __shared__ int sl[8][CAP];
    int tpn = F >> 2;
    int nid = threadIdx.x / tpn;
    int lt  = threadIdx.x - nid*tpn;
    int c4  = lt << 2;
    int node = blockIdx.x * (256/tpn) + nid;
    int deg = min(g_deg[node], CAP);
    for (int e = lt; e < deg; e += tpn) sl[nid][e] = g_lst[node*CAP + e];
    __syncthreads();
    float4 m0 = make_float4(-3.4e38f, -3.4e38f, -3.4e38f, -3.4e38f);
    float4 m1 = m0, m2 = m0, m3 = m0;
    int e = 0;
    for (; e + 4 <= deg; e += 4) {
        float4 v0 = *(const float4*)&p[(size_t)sl[nid][e    ]*F + c4];
        float4 v1 = *(const float4*)&p[(size_t)sl[nid][e + 1]*F + c4];
        float4 v2 = *(const float4*)&p[(size_t)sl[nid][e + 2]*F + c4];
        float4 v3 = *(const float4*)&p[(size_t)sl[nid][e + 3]*F + c4];
        m0.x = fmaxf(m0.x, v0.x); m0.y = fmaxf(m0.y, v0.y);
        m0.z = fmaxf(m0.z, v0.z); m0.w = fmaxf(m0.w, v0.w);
        m1.x = fmaxf(m1.x, v1.x); m1.y = fmaxf(m1.y, v1.y);
        m1.z = fmaxf(m1.z, v1.z); m1.w = fmaxf(m1.w, v1.w);
        m2.x = fmaxf(m2.x, v2.x); m2.y = fmaxf(m2.y, v2.y);
        m2.z = fmaxf(m2.z, v2.z); m2.w = fmaxf(m2.w, v2.w);
        m3.x = fmaxf(m3.x, v3.x); m3.y = fmaxf(m3.y, v3.y);
        m3.z = fmaxf(m3.z, v3.z); m3.w = fmaxf(m3.w, v3.w);
    }
    for (; e < deg; e++) {
        float4 v = *(const float4*)&p[(size_t)sl[nid][e]*F + c4];
        m0.x = fmaxf(m0.x, v.x); m0.y = fmaxf(m0.y, v.y);
        m0.z = fmaxf(m0.z, v.z); m0.w = fmaxf(m0.w, v.w);
    }
    m0.x = fmaxf(fmaxf(m0.x, m1.x), fmaxf(m2.x, m3.x));
    m0.y = fmaxf(fmaxf(m0.y, m1.y), fmaxf(m2.y, m3.y));
    m0.z = fmaxf(fmaxf(m0.z, m1.z), fmaxf(m2.z, m3.z));
    m0.w = fmaxf(fmaxf(m0.w, m1.w), fmaxf(m2.w, m3.w));
    if (deg == 0) m0 = make_float4(0.f, 0.f, 0.f, 0.f);
    *(float4*)&hn[(size_t)node*F + c4] = m0;
}

// ---------------- 3xTF32 tensor-core GEMM (fp32-accurate) -------------------
__global__ void __launch_bounds__(256) k_tgemm(
    const float* __restrict__ A1, const float* __restrict__ B1, int K1,
    const float* __restrict__ A2, const float* __restrict__ B2, int K2,
    const float* __restrict__ bias, float* __restrict__ C,
    int N, int relu_f, int tf32_f, int xtr)
{
    extern __shared__ float tsm[];
    float* sa_h = tsm;                 // [64][68]
    float* sa_l = tsm + 64*68;
    float* sb_h = tsm + 2*64*68;
    float* sb_l = tsm + 3*64*68;
    int t = threadIdx.x, lane = t & 31, warp = t >> 5;
    int wi = warp >> 1, wj = warp & 1;
    int g = lane >> 2, c = lane & 3;
    int m0 = blockIdx.y*64, n0 = blockIdx.x*64;

    float dg[4][4];
    #pragma unroll
    for (int nt = 0; nt < 4; nt++)
        #pragma unroll
        for (int q = 0; q < 4; q++) dg[nt][q] = 0.f;

    int nch = (K1 + K2) >> 6;
    for (int ch = 0; ch < nch; ch++) {
        int k0 = ch*64;
        const float* Ap; const float* Bp; int Kd;
        if (k0 < K1) { Ap = A1 + k0;        Bp = B1 + k0;        Kd = K1; }
        else         { Ap = A2 + (k0 - K1); Bp = B2 + (k0 - K1); Kd = K2; }
        __syncthreads();
        for (int l = t; l < 1024; l += 256) {
            int r = l >> 4, q = (l & 15) << 2;
            float4 v = *(const float4*)&Ap[(size_t)(m0 + r)*Kd + q];
            float4 vh, vl;
            vh.x = tf32r(v.x); vl.x = tf32r(v.x - vh.x);
            vh.y = tf32r(v.y); vl.y = tf32r(v.y - vh.y);
            vh.z = tf32r(v.z); vl.z = tf32r(v.z - vh.z);
            vh.w = tf32r(v.w); vl.w = tf32r(v.w - vh.w);
            *(float4*)&sa_h[r*68 + q] = vh;
            *(float4*)&sa_l[r*68 + q] = vl;
            float4 w = *(const float4*)&Bp[(size_t)(n0 + r)*Kd + q];
            float4 wh, wl;
            wh.x = tf32r(w.x); wl.x = tf32r(w.x - wh.x);
            wh.y = tf32r(w.y); wl.y = tf32r(w.y - wh.y);
            wh.z = tf32r(w.z); wl.z = tf32r(w.z - wh.z);
            wh.w = tf32r(w.w); wl.w = tf32r(w.w - wh.w);
            *(float4*)&sb_h[r*68 + q] = wh;
            *(float4*)&sb_l[r*68 + q] = wl;
        }
        __syncthreads();
        const float* Ah = sa_h + (wi*16)*68;
        const float* Al = sa_l + (wi*16)*68;
        const float* Bh = sb_h + (wj*32)*68;
        const float* Bl = sb_l + (wj*32)*68;
        #pragma unroll
        for (int ks = 0; ks < 8; ks++) {
            int k = ks*8;
            unsigned ah0 = __float_as_uint(Ah[(g    )*68 + k + c    ]);
            unsigned ah1 = __float_as_uint(Ah[(g + 8)*68 + k + c    ]);
            unsigned ah2 = __float_as_uint(Ah[(g    )*68 + k + c + 4]);
            unsigned ah3 = __float_as_uint(Ah[(g + 8)*68 + k + c + 4]);
            unsigned al0 = __float_as_uint(Al[(g    )*68 + k + c    ]);
            unsigned al1 = __float_as_uint(Al[(g + 8)*68 + k + c    ]);
            unsigned al2 = __float_as_uint(Al[(g    )*68 + k + c + 4]);
            unsigned al3 = __float_as_uint(Al[(g + 8)*68 + k + c + 4]);
            #pragma unroll
            for (int nt = 0; nt < 4; nt++) {
                unsigned bh0 = __float_as_uint(Bh[(nt*8 + g)*68 + k + c    ]);
                unsigned bh1 = __float_as_uint(Bh[(nt*8 + g)*68 + k + c + 4]);
                unsigned bl0 = __float_as_uint(Bl[(nt*8 + g)*68 + k + c    ]);
                unsigned bl1 = __float_as_uint(Bl[(nt*8 + g)*68 + k + c + 4]);
                mma8(dg[nt], ah0, ah1, ah2, ah3, bl0, bl1);
                mma8(dg[nt], al0, al1, al2, al3, bh0, bh1);
                mma8(dg[nt], ah0, ah1, ah2, ah3, bh0, bh1);
            }
        }
    }

    #pragma unroll
    for (int nt = 0; nt < 4; nt++) {
        int col = n0 + wj*32 + nt*8 + c*2;
        int r0  = m0 + wi*16 + g, r1 = r0 + 8;
        float bb0 = bias ? bias[col]     : 0.f;
        float bb1 = bias ? bias[col + 1] : 0.f;
        float v00 = dg[nt][0] + bb0, v01 = dg[nt][1] + bb1;
        float v10 = dg[nt][2] + bb0, v11 = dg[nt][3] + bb1;
        if (relu_f) {
            v00 = fmaxf(v00, 0.f); v01 = fmaxf(v01, 0.f);
            v10 = fmaxf(v10, 0.f); v11 = fmaxf(v11, 0.f);
        }
        if (tf32_f) {
            v00 = tf32r(v00); v01 = tf32r(v01);
            v10 = tf32r(v10); v11 = tf32r(v11);
        }
        *(float2*)&C[(size_t)r0*N + col] = make_float2(v00, v01);
        *(float2*)&C[(size_t)r1*N + col] = make_float2(v10, v11);
        if (xtr) {
            g_xt[(size_t)col*XR + r0]       = tf32r(v00);
            g_xt[(size_t)(col + 1)*XR + r0] = tf32r(v01);
            g_xt[(size_t)col*XR + r1]       = tf32r(v10);
            g_xt[(size_t)(col + 1)*XR + r1] = tf32r(v11);
        }
    }
}

// ---------------- relu + row l2norm -----------------------------------------
__global__ void k_relu_l2norm(float* __restrict__ h) {
    int r = blockIdx.x, t = threadIdx.x;
    float v = fmaxf(h[r*HH + t], 0.f);
    float s = v*v;
    #pragma unroll
    for (int o = 16; o; o >>= 1) s += __shfl_down_sync(0xffffffffu, s, o);
    __shared__ float ws[4];
    if ((t & 31) == 0) ws[t >> 5] = s;
    __syncthreads();
    float tot = ws[0] + ws[1] + ws[2] + ws[3];
    float nrm = fmaxf(sqrtf(tot), 1e-12f);
    h[r*HH + t] = v / nrm;
}

// ---------------- SMOTE NN phase: grid (32 i-tiles, 4 j-chunks) -------------
__global__ void __launch_bounds__(256) k_smote_nn() {
    __shared__ float4 ci[32*33];
    __shared__ float4 cj[32*33];
    __shared__ float  sqj[32];
    int t = threadIdx.x;
    int i0 = blockIdx.x*32;
    int jbase = blockIdx.y*256;
    int ri = t >> 3, s = t & 7;

    const float4* srci = (const float4*)&g_x[(size_t)i0*HH];
    for (int l = t; l < 32*32; l += 256) {
        int r = l >> 5, kq = l & 31;
        ci[r*33 + kq] = srci[l];
    }
    __syncthreads();

    float sqi;
    {
        float ps = 0.f;
        #pragma unroll
        for (int u = 0; u < 4; u++) {
            float4 v = ci[ri*33 + s*4 + u];
            ps += v.x*v.x + v.y*v.y + v.z*v.z + v.w*v.w;
        }
        #pragma unroll
        for (int o = 1; o <= 4; o <<= 1) ps += __shfl_xor_sync(0xffffffffu, ps, o);
        sqi = ps;
    }
    int   gi  = i0 + ri;
    float best = 3.4e38f; int bestj = 0x7fffffff;

    for (int j0 = jbase; j0 < jbase + 256; j0 += 32) {
        __syncthreads();
        const float4* srcj = (const float4*)&g_x[(size_t)j0*HH];
        for (int l = t; l < 32*32; l += 256) {
            int r = l >> 5, kq = l & 31;
            cj[r*33 + kq] = srcj[l];
        }
        __syncthreads();
        {
            float ps = 0.f;
            #pragma unroll
            for (int u = 0; u < 4; u++) {
                float4 v = cj[ri*33 + s*4 + u];
                ps += v.x*v.x + v.y*v.y + v.z*v.z + v.w*v.w;
            }
            #pragma unroll
            for (int o = 1; o <= 4; o <<= 1) ps += __shfl_xor_sync(0xffffffffu, ps, o);
            if (s == 0) sqj[ri] = ps;
        }
        __syncthreads();

        float d0=0.f,d1=0.f,d2=0.f,d3=0.f;
        #pragma unroll
        for (int kq = 0; kq < 32; kq++) {
            float4 a  = ci[ri*33 + kq];
            float4 b0 = cj[(s     )*33 + kq];
            float4 b1 = cj[(s +  8)*33 + kq];
            float4 b2 = cj[(s + 16)*33 + kq];
            float4 b3 = cj[(s + 24)*33 + kq];
            d0 += a.x*b0.x + a.y*b0.y + a.z*b0.z + a.w*b0.w;
            d1 += a.x*b1.x + a.y*b1.y + a.z*b1.z + a.w*b1.w;
            d2 += a.x*b2.x + a.y*b2.y + a.z*b2.z + a.w*b2.w;
            d3 += a.x*b3.x + a.y*b3.y + a.z*b3.z + a.w*b3.w;
        }
        float dd[4] = {d0,d1,d2,d3};
        #pragma unroll
        for (int m = 0; m < 4; m++) {
            int j = j0 + s + 8*m;
            float dv = fmaxf(sqi + sqj[s + 8*m] - 2.f*dd[m], 0.f);
            if (j != gi) {
                if (dv < best || (dv == best && j < bestj)) { best = dv; bestj = j; }
            }
        }
    }
    #pragma unroll
    for (int o = 4; o; o >>= 1) {
        float ob = __shfl_down_sync(0xffffffffu, best, o);
        int   oj = __shfl_down_sync(0xffffffffu, bestj, o);
        if (ob < best || (ob == best && oj < bestj)) { best = ob; bestj = oj; }
    }
    if (s == 0) {
        unsigned long long pk = ((unsigned long long)__float_as_uint(best) << 32)
                              | (unsigned)bestj;
        g_nnp[(size_t)gi*4 + blockIdx.y] = pk;
    }
}

// ---------------- SMOTE interp: combine 4 chunks, write synth + xt ----------
__global__ void __launch_bounds__(256) k_smote_int(const float* __restrict__ gaps) {
    int t = threadIdx.x;
    int r  = t >> 3;
    int gr = blockIdx.x*32 + r;
    int c0 = (t & 7) * 16;
    unsigned long long p0 = g_nnp[(size_t)gr*4 + 0];
    unsigned long long p1 = g_nnp[(size_t)gr*4 + 1];
    unsigned long long p2 = g_nnp[(size_t)gr*4 + 2];
    unsigned long long p3 = g_nnp[(size_t)gr*4 + 3];
    unsigned long long pm = min(min(p0, p1), min(p2, p3));
    int nn = (int)(pm & 0xffffffffu);
    float ga = gaps[gr*REPC + 0], gb = gaps[gr*REPC + 1];
    int ra = NV + 2*gr, rb = ra + 1;
    #pragma unroll
    for (int u = 0; u < 16; u += 4) {
        float4 cv = *(const float4*)&g_x[(size_t)gr*HH + c0 + u];
        float4 nv = *(const float4*)&g_x[(size_t)nn*HH + c0 + u];
        float4 oa, ob;
        oa.x = cv.x + ga*(nv.x - cv.x); oa.y = cv.y + ga*(nv.y - cv.y);
        oa.z = cv.z + ga*(nv.z - cv.z); oa.w = cv.w + ga*(nv.w - cv.w);
        ob.x = cv.x + gb*(nv.x - cv.x); ob.y = cv.y + gb*(nv.y - cv.y);
        ob.z = cv.z + gb*(nv.z - cv.z); ob.w = cv.w + gb*(nv.w - cv.w);
        *(float4*)&g_x[(size_t)ra*HH + c0 + u] = oa;
        *(float4*)&g_x[(size_t)rb*HH + c0 + u] = ob;
        int h = c0 + u;
        g_xt[(size_t)(h+0)*XR + ra] = tf32r(oa.x);
        g_xt[(size_t)(h+1)*XR + ra] = tf32r(oa.y);
        g_xt[(size_t)(h+2)*XR + ra] = tf32r(oa.z);
        g_xt[(size_t)(h+3)*XR + ra] = tf32r(oa.w);
        g_xt[(size_t)(h+0)*XR + rb] = tf32r(ob.x);
        g_xt[(size_t)(h+1)*XR + rb] = tf32r(ob.y);
        g_xt[(size_t)(h+2)*XR + rb] = tf32r(ob.z);
        g_xt[(size_t)(h+3)*XR + rb] = tf32r(ob.w);
    }
}

// ---------------- fused tf32-MMA (round-9 proven config) --------------------
// gram -> sigmoid -> split-loss -> threshold -> neigh; 64-row tiles, 2 blk/SM.
__global__ void __launch_bounds__(256, 2) k_fused5(const float* __restrict__ adj) {
    extern __shared__ float dsm[];
    float* soi = dsm;                    // [64][132] out_i
    float* buf = dsm + 64*132;           // union: out_j [64][132] / xT [128][68]
    float* sp  = buf + 128*68;           // [64][68] thresholded P (tf32)
    float* srs = sp + 64*68;             // [2][64] rowsum partials
    float* lred = srs + 128;             // [3][8] cnt / S_non / S_edge

    int t    = threadIdx.x;
    int lane = t & 31, warp = t >> 5;
    int wi = warp >> 1, wj = warp & 1;
    int g  = lane >> 2, c = lane & 3;
    int i0 = blockIdx.x * 64;
    int chunk = blockIdx.y;
    int jbase = chunk * CHJ;
    bool lossi = (i0 < NV) && (chunk < 2);
    unsigned bufb = (unsigned)__cvta_generic_to_shared(buf);

    {
        const float4* src = (const float4*)&g_out[(size_t)i0*HH];
        unsigned soib = (unsigned)__cvta_generic_to_shared(soi);
        for (int l = t; l < 2048; l += 256) {
            int r = l >> 5, kq = l & 31;
            cpa16(soib + (unsigned)(r*33 + kq)*16u, src + l);
        }
    }

    float nacc[8][4];
    #pragma unroll
    for (int nt = 0; nt < 8; nt++)
        #pragma unroll
        for (int q = 0; q < 4; q++) nacc[nt][q] = 0.f;
    float rsum0 = 0.f, rsum1 = 0.f;
    float lcnt = 0.f, lsnon = 0.f, lsedge = 0.f;

    const float* Ab = soi + (wi*16)*132;
    const float* Pb = sp  + (wi*16)*68;

    for (int jt = 0; jt < CHJ/64; jt++) {
        int j0 = jbase + jt*64;
        __syncthreads();   // protect buf from previous neigh readers
        {
            const float4* src = (const float4*)&g_out[(size_t)j0*HH];
            for (int l = t; l < 2048; l += 256) {
                int r = l >> 5, kq = l & 31;
                cpa16(bufb + (unsigned)(r*33 + kq)*16u, src + l);
            }
            cpa_commit_wait();
        }
        __syncthreads();

        // ---- gram MMA ----
        float dg[4][4];
        #pragma unroll
        for (int nt = 0; nt < 4; nt++)
            #pragma unroll
            for (int q = 0; q < 4; q++) dg[nt][q] = 0.f;
        const float* Bb = buf + (wj*32)*132;
        #pragma unroll 4
        for (int ks = 0; ks < 16; ks++) {
            int k = ks*8;
            unsigned a0 = __float_as_uint(Ab[(g    )*132 + k + c    ]);
            unsigned a1 = __float_as_uint(Ab[(g + 8)*132 + k + c    ]);
            unsigned a2 = __float_as_uint(Ab[(g    )*132 + k + c + 4]);
            unsigned a3 = __float_as_uint(Ab[(g + 8)*132 + k + c + 4]);
            #pragma unroll
            for (int nt = 0; nt < 4; nt++) {
                unsigned b0 = __float_as_uint(Bb[(nt*8 + g)*132 + k + c    ]);
                unsigned b1 = __float_as_uint(Bb[(nt*8 + g)*132 + k + c + 4]);
                mma8(dg[nt], a0, a1, a2, a3, b0, b1);
            }
        }

        // ---- epilogue: sigmoid, split loss, rowsum, write P ----
        #pragma unroll
        for (int nt = 0; nt < 4; nt++) {
            int lj = wj*32 + nt*8 + c*2;
            int gj = j0 + lj;
            int r0 = i0 + wi*16 + g, r1 = r0 + 8;
            float p0 = 1.f/(1.f + __expf(-dg[nt][0]));
            float p1 = 1.f/(1.f + __expf(-dg[nt][1]));
            float p2 = 1.f/(1.f + __expf(-dg[nt][2]));
            float p3 = 1.f/(1.f + __expf(-dg[nt][3]));
            if (lossi) {
                float2 a0v = *(const float2*)&adj[(size_t)r0*NV + gj];
                float2 a1v = *(const float2*)&adj[(size_t)r1*NV + gj];
                float e0 = p0 - a0v.x, e1 = p1 - a0v.y;
                float e2 = p2 - a1v.x, e3 = p3 - a1v.y;
                float q0 = e0*e0, q1 = e1*e1, q2 = e2*e2, q3 = e3*e3;
                bool z0 = (a0v.x == 0.f), z1 = (a0v.y == 0.f);
                bool z2 = (a1v.x == 0.f), z3 = (a1v.y == 0.f);
                lcnt   += (z0?0.f:1.f) + (z1?0.f:1.f) + (z2?0.f:1.f) + (z3?0.f:1.f);
                lsnon  += (z0?q0:0.f) + (z1?q1:0.f) + (z2?q2:0.f) + (z3?q3:0.f);
                lsedge += (z0?0.f:q0) + (z1?0.f:q1) + (z2?0.f:q2) + (z3?0.f:q3);
            }
            float t0 = (p0 >= 0.5f) ? p0 : 0.f;
            float t1 = (p1 >= 0.5f) ? p1 : 0.f;
            float t2 = (p2 >= 0.5f) ? p2 : 0.f;
            float t3 = (p3 >= 0.5f) ? p3 : 0.f;
            rsum0 += t0 + t1;  rsum1 += t2 + t3;
            *(float2*)&sp[(wi*16 + g    )*68 + lj] = make_float2(tf32r(t0), tf32r(t1));
            *(float2*)&sp[(wi*16 + g + 8)*68 + lj] = make_float2(tf32r(t2), tf32r(t3));
        }
        __syncthreads();   // sp complete; buf free

        {
            const float* srcb = g_xt + j0;
            for (int l = t; l < 2048; l += 256) {
                int h = l >> 4, q = l & 15;
                cpa16(bufb + (unsigned)(h*17 + q)*16u, &srcb[(size_t)h*XR + q*4]);
            }
            cpa_commit_wait();
        }
        __syncthreads();

        // ---- neigh MMA ----
        #pragma unroll 2
        for (int ks = 0; ks < 8; ks++) {
            int k = ks*8;
            unsigned a0 = __float_as_uint(Pb[(g    )*68 + k + c    ]);
            unsigned a1 = __float_as_uint(Pb[(g + 8)*68 + k + c    ]);
            unsigned a2 = __float_as_uint(Pb[(g    )*68 + k + c + 4]);
            unsigned a3 = __float_as_uint(Pb[(g + 8)*68 + k + c + 4]);
            #pragma unroll
            for (int nt = 0; nt < 8; nt++) {
                unsigned b0 = __float_as_uint(buf[(wj*64 + nt*8 + g)*68 + k + c    ]);
                unsigned b1 = __float_as_uint(buf[(wj*64 + nt*8 + g)*68 + k + c + 4]);
                mma8(nacc[nt], a0, a1, a2, a3, b0, b1);
            }
        }
    }

    // ---- write neigh partials (exclusive per chunk) ----
    size_t cb = (size_t)chunk * XR;
    #pragma unroll
    for (int nt = 0; nt < 8; nt++) {
        int h = wj*64 + nt*8 + c*2;
        int r0 = i0 + wi*16 + g, r1 = r0 + 8;
        *(float2*)&g_ng4[(cb + r0)*HH + h] = make_float2(nacc[nt][0], nacc[nt][1]);
        *(float2*)&g_ng4[(cb + r1)*HH + h] = make_float2(nacc[nt][2], nacc[nt][3]);
    }

    // ---- rowsums ----
    #pragma unroll
    for (int o = 1; o <= 2; o <<= 1) {
        rsum0 += __shfl_xor_sync(0xffffffffu, rsum0, o);
        rsum1 += __shfl_xor_sync(0xffffffffu, rsum1, o);
    }
    if (c == 0) {
        srs[wj*64 + wi*16 + g    ] = rsum0;
        srs[wj*64 + wi*16 + g + 8] = rsum1;
    }
    // ---- count + split-loss reduction ----
    #pragma unroll
    for (int o = 16; o; o >>= 1) {
        lcnt   += __shfl_down_sync(0xffffffffu, lcnt,   o);
        lsnon  += __shfl_down_sync(0xffffffffu, lsnon,  o);
        lsedge += __shfl_down_sync(0xffffffffu, lsedge, o);
    }
    if (lane == 0) {
        lred[warp]      = lcnt;
        lred[8 + warp]  = lsnon;
        lred[16 + warp] = lsedge;
    }
    __syncthreads();
    if (t < 64) g_rs4[cb + i0 + t] = srs[t] + srs[64 + t];
    if (t == 0 && lossi) {
        float sc = 0.f, sn = 0.f, se = 0.f;
        for (int q = 0; q < 8; q++) { sc += lred[q]; sn += lred[8+q]; se += lred[16+q]; }
        atomicAdd(&g_scal[0], sc);
        atomicAdd(&g_scal[2], sn);
        atomicAdd(&g_scal[3], se);
    }
}

// ---------------- merged classifier: weff + logits + y + loss ---------------
__global__ void __launch_bounds__(256) k_final2(
    const float* __restrict__ Wclf, const float* __restrict__ Wconv,
    const float* __restrict__ bclf, const int* __restrict__ labels,
    float* __restrict__ ob)
{
    __shared__ float sw[512];
    int t = threadIdx.x, lane = t & 31, warp = t >> 5;
    for (int idx = t; idx < 512; idx += 256) {
        int cc = idx >> 8, k = idx & 255;
        float s = 0.f;
        for (int o = 0; o < HH; o++) s += Wclf[cc*HH + o] * Wconv[o*256 + k];
        sw[idx] = s;
    }
    __syncthreads();
    int i0 = blockIdx.x*32;
    float b0 = bclf[0], b1 = bclf[1];
    #pragma unroll
    for (int q = 0; q < 4; q++) {
        int w = i0 + warp*4 + q;
        float rs = g_rs4[w] + g_rs4[XR + w] + g_rs4[2*XR + w];
        float inv = 1.f / (rs + 1.f);
        float l0 = 0.f, l1 = 0.f;
        for (int k = lane; k < HH; k += 32) {
            float xv = g_x[(size_t)w*HH + k];
            float nv = (g_ng4[(size_t)w*HH + k] + g_ng4[((size_t)XR + w)*HH + k]
                      + g_ng4[((size_t)2*XR + w)*HH + k]) * inv;
            l0 += xv*sw[k]       + nv*sw[128 + k];
            l1 += xv*sw[256 + k] + nv*sw[256 + 128 + k];
        }
        #pragma unroll
        for (int o = 16; o; o >>= 1) {
            l0 += __shfl_down_sync(0xffffffffu, l0, o);
            l1 += __shfl_down_sync(0xffffffffu, l1, o);
        }
        if (lane == 0) {
            ob[w*2 + 0] = l0 + b0;
            ob[w*2 + 1] = l1 + b1;
        }
    }
    if (t < 32) {
        int gr = i0 + t;
        ob[XR*2 + gr] = (gr < NV) ? (float)labels[gr] : 1.f;
    }
    if (blockIdx.x == 0 && t == 0) {
        float e = g_scal[0];
        float negw = e / (16777216.f - e);
        ob[XR*2 + XR] = g_scal[3] + negw * g_scal[2];
    }
}

// ---------------- launcher --------------------------------------------------
extern "C" void kernel_launch(void* const* d_in, const int* in_sizes, int n_in,
                              void* d_out, int out_size) {
    const float* feat     = (const float*)d_in[0];
    const float* adj      = (const float*)d_in[1];
    const int*   src      = (const int*)  d_in[2];
    const int*   dst      = (const int*)  d_in[3];
    const int*   labels   = (const int*)  d_in[4];
    const float* W_pool0  = (const float*)d_in[5];
    const float* b_pool0  = (const float*)d_in[6];
    const float* W_self0  = (const float*)d_in[7];
    const float* W_neigh0 = (const float*)d_in[8];
    const float* b0       = (const float*)d_in[9];
    const float* W_pool1  = (const float*)d_in[10];
    const float* b_pool1  = (const float*)d_in[11];
    const float* W_self1  = (const float*)d_in[12];
    const float* W_neigh1 = (const float*)d_in[13];
    const float* b1       = (const float*)d_in[14];
    const float* de_w     = (const float*)d_in[15];
    const float* W_conv   = (const float*)d_in[16];
    const float* W_clf    = (const float*)d_in[17];
    const float* b_clf    = (const float*)d_in[18];
    const float* gaps     = (const float*)d_in[19];
    int E = in_sizes[2];
    float* ob = (float*)d_out;

    float *p0, *hn0, *hh, *p1, *hn1, *xv, *ov;
    cudaGetSymbolAddress((void**)&p0,  g_p0);
    cudaGetSymbolAddress((void**)&hn0, g_hn0);
    cudaGetSymbolAddress((void**)&hh,  g_h);
    cudaGetSymbolAddress((void**)&p1,  g_p1);
    cudaGetSymbolAddress((void**)&hn1, g_hn1);
    cudaGetSymbolAddress((void**)&xv,  g_x);
    cudaGetSymbolAddress((void**)&ov,  g_out);

    const int FUSED_SMEM = (64*132 + 128*68 + 64*68 + 128 + 24) * 4;  // 86624 B
    const int TGEMM_SMEM = 4*64*68*4;                                 // 69632 B
    cudaFuncSetAttribute(k_fused5, cudaFuncAttributeMaxDynamicSharedMemorySize, FUSED_SMEM);
    cudaFuncSetAttribute(k_tgemm,  cudaFuncAttributeMaxDynamicSharedMemorySize, TGEMM_SMEM);

    k_init<<<(NV+255)/256, 256>>>();
    k_build<<<(E+255)/256, 256>>>(src, dst, E);

    // layer 0
    k_tgemm<<<dim3(FIN/64, NV/64), 256, TGEMM_SMEM>>>(feat, W_pool0, FIN,
        (const float*)0, (const float*)0, 0, b_pool0, p0, FIN, 1, 0, 0);
    k_gmax4<<<NV/4, 256>>>(p0, hn0, FIN);
    k_tgemm<<<dim3(HH/64, NV/64), 256, TGEMM_SMEM>>>(feat, W_self0, FIN, hn0, W_neigh0, FIN,
        b0, hh, HH, 0, 0, 0);
    k_relu_l2norm<<<NV, HH>>>(hh);

    // layer 1
    k_tgemm<<<dim3(HH/64, NV/64), 256, TGEMM_SMEM>>>(hh, W_pool1, HH,
        (const float*)0, (const float*)0, 0, b_pool1, p1, HH, 1, 0, 0);
    k_gmax4<<<NV/8, 256>>>(p1, hn1, HH);
    k_tgemm<<<dim3(HH/64, NV/64), 256, TGEMM_SMEM>>>(hh, W_self1, HH, hn1, W_neigh1, HH,
        b1, xv, HH, 0, 0, 1);   // also writes g_xt rows < NV

    // SMOTE (4-way parallel NN + interp writing synth rows + g_xt)
    k_smote_nn<<<dim3(MINC/32, 4), 256>>>();
    k_smote_int<<<MINC/32, 256>>>(gaps);

    // decoder input (3xTF32, tf32-rounded epilogue feeds fused pass directly)
    k_tgemm<<<dim3(HH/64, XR/64), 256, TGEMM_SMEM>>>(xv, de_w, HH,
        (const float*)0, (const float*)0, 0, (const float*)0, ov, HH, 0, 1, 0);

    // big fused pass (tensor cores; 64-row tiles, 2 blocks/SM)
    k_fused5<<<dim3(XR/64, NCH), 256, FUSED_SMEM>>>(adj);

    // merged classifier + y + loss
    k_final2<<<XR/32, 256>>>(W_clf, W_conv, b_clf, labels, ob);
}

// round 16
// speedup vs baseline: 1.4481x; 1.4481x over previous
#include <cuda_runtime.h>
#include <math.h>

#define NV    4096
#define FIN   256
#define HH    128
#define MINC  1024
#define REPC  2
#define XR    6144   // NV + MINC*REPC
#define NCH   3      // j-chunks in fused pass
#define CHJ   (XR/NCH)   // 2048
#define CAP   128    // per-node adjacency capacity (mean deg ~17)

// ---------------- scratch (static __device__, no allocs) ----------------
__device__ __align__(16) float g_p0 [NV*FIN];
__device__ __align__(16) float g_hn0[NV*FIN];
__device__ __align__(16) float g_h  [NV*HH];
__device__ __align__(16) float g_p1 [NV*HH];
__device__ __align__(16) float g_hn1[NV*HH];
__device__ __align__(16) float g_x  [XR*HH];
__device__ __align__(16) float g_xt [HH*XR];          // transposed + tf32-rounded
__device__ __align__(16) float g_out[XR*HH];
__device__ __align__(16) float g_ng4[(size_t)NCH*XR*HH];
__device__ __align__(16) float g_rs4[NCH*XR];
__device__ __align__(16) float g_scal[4];     // 0: edge count, 2: S_non, 3: S_edge
__device__ int g_deg[NV];
__device__ int g_lst[NV*CAP];
__device__ unsigned long long g_nnp[MINC*4];  // packed (d2bits<<32 | j) per j-chunk

__device__ __forceinline__ float tf32r(float x) {
    unsigned u;
    asm("cvt.rna.tf32.f32 %0, %1;" : "=r"(u) : "f"(x));
    return __uint_as_float(u);
}

__device__ __forceinline__ void mma8(float* d, unsigned a0, unsigned a1, unsigned a2,
                                     unsigned a3, unsigned b0, unsigned b1) {
    asm volatile("mma.sync.aligned.m16n8k8.row.col.f32.tf32.tf32.f32 "
                 "{%0,%1,%2,%3}, {%4,%5,%6,%7}, {%8,%9}, {%0,%1,%2,%3};"
                 : "+f"(d[0]), "+f"(d[1]), "+f"(d[2]), "+f"(d[3])
                 : "r"(a0), "r"(a1), "r"(a2), "r"(a3), "r"(b0), "r"(b1));
}

__device__ __forceinline__ void cpa16(unsigned s, const void* g) {
    asm volatile("cp.async.cg.shared.global [%0], [%1], 16;" :: "r"(s), "l"(g));
}
__device__ __forceinline__ void cpa_commit_wait() {
    asm volatile("cp.async.commit_group;");
    asm volatile("cp.async.wait_group 0;" ::: "memory");
}

// ---------------- init ------------------------------------------------------
__global__ void k_init() {
    int i = blockIdx.x*blockDim.x + threadIdx.x;
    if (i < NV) g_deg[i] = 0;
    if (i == 0) { g_scal[0] = 0.f; g_scal[2] = 0.f; g_scal[3] = 0.f; }
}

// ---------------- CSR-ish build: per-dst source lists -----------------------
__global__ void k_build(const int* __restrict__ src, const int* __restrict__ dst, int E) {
    int e = blockIdx.x*blockDim.x + threadIdx.x;
    if (e >= E) return;
    int d = dst[e];
    int slot = atomicAdd(&g_deg[d], 1);
    if (slot < CAP) g_lst[d*CAP + slot] = src[e];
}

// ---------------- gather segment-max, float4-wide ----------------------------
__global__ void k_gmax4(const float* __restrict__ p, float* __restrict__ hn, int F) {
    __shared__ int sl[8][CAP];
    int tpn = F >> 2;
    int nid = threadIdx.x / tpn;
    int lt  = threadIdx.x - nid*tpn;
    int c4  = lt << 2;
    int node = blockIdx.x * (256/tpn) + nid;
    int deg = min(g_deg[node], CAP);
    for (int e = lt; e < deg; e += tpn) sl[nid][e] = g_lst[node*CAP + e];
    __syncthreads();
    float4 m = make_float4(-3.4e38f, -3.4e38f, -3.4e38f, -3.4e38f);
    for (int e = 0; e < deg; e++) {
        float4 v = *(const float4*)&p[(size_t)sl[nid][e]*F + c4];
        m.x = fmaxf(m.x, v.x); m.y = fmaxf(m.y, v.y);
        m.z = fmaxf(m.z, v.z); m.w = fmaxf(m.w, v.w);
    }
    if (deg == 0) m = make_float4(0.f, 0.f, 0.f, 0.f);
    *(float4*)&hn[(size_t)node*F + c4] = m;
}

// ---------------- 3xTF32 tensor-core GEMM (fp32-accurate) -------------------
__global__ void __launch_bounds__(256) k_tgemm(
    const float* __restrict__ A1, const float* __restrict__ B1, int K1,
    const float* __restrict__ A2, const float* __restrict__ B2, int K2,
    const float* __restrict__ bias, float* __restrict__ C,
    int N, int relu_f, int tf32_f, int xtr)
{
    extern __shared__ float tsm[];
    float* sa_h = tsm;                 // [64][68]
    float* sa_l = tsm + 64*68;
    float* sb_h = tsm + 2*64*68;
    float* sb_l = tsm + 3*64*68;
    int t = threadIdx.x, lane = t & 31, warp = t >> 5;
    int wi = warp >> 1, wj = warp & 1;
    int g = lane >> 2, c = lane & 3;
    int m0 = blockIdx.y*64, n0 = blockIdx.x*64;

    float dg[4][4];
    #pragma unroll
    for (int nt = 0; nt < 4; nt++)
        #pragma unroll
        for (int q = 0; q < 4; q++) dg[nt][q] = 0.f;

    int nch = (K1 + K2) >> 6;
    for (int ch = 0; ch < nch; ch++) {
        int k0 = ch*64;
        const float* Ap; const float* Bp; int Kd;
        if (k0 < K1) { Ap = A1 + k0;        Bp = B1 + k0;        Kd = K1; }
        else         { Ap = A2 + (k0 - K1); Bp = B2 + (k0 - K1); Kd = K2; }
        __syncthreads();
        for (int l = t; l < 1024; l += 256) {
            int r = l >> 4, q = (l & 15) << 2;
            float4 v = *(const float4*)&Ap[(size_t)(m0 + r)*Kd + q];
            float4 vh, vl;
            vh.x = tf32r(v.x); vl.x = tf32r(v.x - vh.x);
            vh.y = tf32r(v.y); vl.y = tf32r(v.y - vh.y);
            vh.z = tf32r(v.z); vl.z = tf32r(v.z - vh.z);
            vh.w = tf32r(v.w); vl.w = tf32r(v.w - vh.w);
            *(float4*)&sa_h[r*68 + q] = vh;
            *(float4*)&sa_l[r*68 + q] = vl;
            float4 w = *(const float4*)&Bp[(size_t)(n0 + r)*Kd + q];
            float4 wh, wl;
            wh.x = tf32r(w.x); wl.x = tf32r(w.x - wh.x);
            wh.y = tf32r(w.y); wl.y = tf32r(w.y - wh.y);
            wh.z = tf32r(w.z); wl.z = tf32r(w.z - wh.z);
            wh.w = tf32r(w.w); wl.w = tf32r(w.w - wh.w);
            *(float4*)&sb_h[r*68 + q] = wh;
            *(float4*)&sb_l[r*68 + q] = wl;
        }
        __syncthreads();
        const float* Ah = sa_h + (wi*16)*68;
        const float* Al = sa_l + (wi*16)*68;
        const float* Bh = sb_h + (wj*32)*68;
        const float* Bl = sb_l + (wj*32)*68;
        #pragma unroll
        for (int ks = 0; ks < 8; ks++) {
            int k = ks*8;
            unsigned ah0 = __float_as_uint(Ah[(g    )*68 + k + c    ]);
            unsigned ah1 = __float_as_uint(Ah[(g + 8)*68 + k + c    ]);
            unsigned ah2 = __float_as_uint(Ah[(g    )*68 + k + c + 4]);
            unsigned ah3 = __float_as_uint(Ah[(g + 8)*68 + k + c + 4]);
            unsigned al0 = __float_as_uint(Al[(g    )*68 + k + c    ]);
            unsigned al1 = __float_as_uint(Al[(g + 8)*68 + k + c    ]);
            unsigned al2 = __float_as_uint(Al[(g    )*68 + k + c + 4]);
            unsigned al3 = __float_as_uint(Al[(g + 8)*68 + k + c + 4]);
            #pragma unroll
            for (int nt = 0; nt < 4; nt++) {
                unsigned bh0 = __float_as_uint(Bh[(nt*8 + g)*68 + k + c    ]);
                unsigned bh1 = __float_as_uint(Bh[(nt*8 + g)*68 + k + c + 4]);
                unsigned bl0 = __float_as_uint(Bl[(nt*8 + g)*68 + k + c    ]);
                unsigned bl1 = __float_as_uint(Bl[(nt*8 + g)*68 + k + c + 4]);
                mma8(dg[nt], ah0, ah1, ah2, ah3, bl0, bl1);
                mma8(dg[nt], al0, al1, al2, al3, bh0, bh1);
                mma8(dg[nt], ah0, ah1, ah2, ah3, bh0, bh1);
            }
        }
    }

    #pragma unroll
    for (int nt = 0; nt < 4; nt++) {
        int col = n0 + wj*32 + nt*8 + c*2;
        int r0  = m0 + wi*16 + g, r1 = r0 + 8;
        float bb0 = bias ? bias[col]     : 0.f;
        float bb1 = bias ? bias[col + 1] : 0.f;
        float v00 = dg[nt][0] + bb0, v01 = dg[nt][1] + bb1;
        float v10 = dg[nt][2] + bb0, v11 = dg[nt][3] + bb1;
        if (relu_f) {
            v00 = fmaxf(v00, 0.f); v01 = fmaxf(v01, 0.f);
            v10 = fmaxf(v10, 0.f); v11 = fmaxf(v11, 0.f);
        }
        if (tf32_f) {
            v00 = tf32r(v00); v01 = tf32r(v01);
            v10 = tf32r(v10); v11 = tf32r(v11);
        }
        *(float2*)&C[(size_t)r0*N + col] = make_float2(v00, v01);
        *(float2*)&C[(size_t)r1*N + col] = make_float2(v10, v11);
        if (xtr) {
            g_xt[(size_t)col*XR + r0]       = tf32r(v00);
            g_xt[(size_t)(col + 1)*XR + r0] = tf32r(v01);
            g_xt[(size_t)col*XR + r1]       = tf32r(v10);
            g_xt[(size_t)(col + 1)*XR + r1] = tf32r(v11);
        }
    }
}

// ---------------- relu + row l2norm -----------------------------------------
__global__ void k_relu_l2norm(float* __restrict__ h) {
    int r = blockIdx.x, t = threadIdx.x;
    float v = fmaxf(h[r*HH + t], 0.f);
    float s = v*v;
    #pragma unroll
    for (int o = 16; o; o >>= 1) s += __shfl_down_sync(0xffffffffu, s, o);
    __shared__ float ws[4];
    if ((t & 31) == 0) ws[t >> 5] = s;
    __syncthreads();
    float tot = ws[0] + ws[1] + ws[2] + ws[3];
    float nrm = fmaxf(sqrtf(tot), 1e-12f);
    h[r*HH + t] = v / nrm;
}

// ---------------- SMOTE NN phase: grid (32 i-tiles, 4 j-chunks) -------------
__global__ void __launch_bounds__(256) k_smote_nn() {
    __shared__ float4 ci[32*33];
    __shared__ float4 cj[32*33];
    __shared__ float  sqj[32];
    int t = threadIdx.x;
    int i0 = blockIdx.x*32;
    int jbase = blockIdx.y*256;
    int ri = t >> 3, s = t & 7;

    const float4* srci = (const float4*)&g_x[(size_t)i0*HH];
    for (int l = t; l < 32*32; l += 256) {
        int r = l >> 5, kq = l & 31;
        ci[r*33 + kq] = srci[l];
    }
    __syncthreads();

    float sqi;
    {
        float ps = 0.f;
        #pragma unroll
        for (int u = 0; u < 4; u++) {
            float4 v = ci[ri*33 + s*4 + u];
            ps += v.x*v.x + v.y*v.y + v.z*v.z + v.w*v.w;
        }
        #pragma unroll
        for (int o = 1; o <= 4; o <<= 1) ps += __shfl_xor_sync(0xffffffffu, ps, o);
        sqi = ps;
    }
    int   gi  = i0 + ri;
    float best = 3.4e38f; int bestj = 0x7fffffff;

    for (int j0 = jbase; j0 < jbase + 256; j0 += 32) {
        __syncthreads();
        const float4* srcj = (const float4*)&g_x[(size_t)j0*HH];
        for (int l = t; l < 32*32; l += 256) {
            int r = l >> 5, kq = l & 31;
            cj[r*33 + kq] = srcj[l];
        }
        __syncthreads();
        {
            float ps = 0.f;
            #pragma unroll
            for (int u = 0; u < 4; u++) {
                float4 v = cj[ri*33 + s*4 + u];
                ps += v.x*v.x + v.y*v.y + v.z*v.z + v.w*v.w;
            }
            #pragma unroll
            for (int o = 1; o <= 4; o <<= 1) ps += __shfl_xor_sync(0xffffffffu, ps, o);
            if (s == 0) sqj[ri] = ps;
        }
        __syncthreads();

        float d0=0.f,d1=0.f,d2=0.f,d3=0.f;
        #pragma unroll
        for (int kq = 0; kq < 32; kq++) {
            float4 a  = ci[ri*33 + kq];
            float4 b0 = cj[(s     )*33 + kq];
            float4 b1 = cj[(s +  8)*33 + kq];
            float4 b2 = cj[(s + 16)*33 + kq];
            float4 b3 = cj[(s + 24)*33 + kq];
            d0 += a.x*b0.x + a.y*b0.y + a.z*b0.z + a.w*b0.w;
            d1 += a.x*b1.x + a.y*b1.y + a.z*b1.z + a.w*b1.w;
            d2 += a.x*b2.x + a.y*b2.y + a.z*b2.z + a.w*b2.w;
            d3 += a.x*b3.x + a.y*b3.y + a.z*b3.z + a.w*b3.w;
        }
        float dd[4] = {d0,d1,d2,d3};
        #pragma unroll
        for (int m = 0; m < 4; m++) {
            int j = j0 + s + 8*m;
            float dv = fmaxf(sqi + sqj[s + 8*m] - 2.f*dd[m], 0.f);
            if (j != gi) {
                if (dv < best || (dv == best && j < bestj)) { best = dv; bestj = j; }
            }
        }
    }
    #pragma unroll
    for (int o = 4; o; o >>= 1) {
        float ob = __shfl_down_sync(0xffffffffu, best, o);
        int   oj = __shfl_down_sync(0xffffffffu, bestj, o);
        if (ob < best || (ob == best && oj < bestj)) { best = ob; bestj = oj; }
    }
    if (s == 0) {
        unsigned long long pk = ((unsigned long long)__float_as_uint(best) << 32)
                              | (unsigned)bestj;
        g_nnp[(size_t)gi*4 + blockIdx.y] = pk;
    }
}

// ---------------- SMOTE interp: combine 4 chunks, write synth + xt ----------
__global__ void __launch_bounds__(256) k_smote_int(const float* __restrict__ gaps) {
    int t = threadIdx.x;
    int r  = t >> 3;
    int gr = blockIdx.x*32 + r;
    int c0 = (t & 7) * 16;
    unsigned long long p0 = g_nnp[(size_t)gr*4 + 0];
    unsigned long long p1 = g_nnp[(size_t)gr*4 + 1];
    unsigned long long p2 = g_nnp[(size_t)gr*4 + 2];
    unsigned long long p3 = g_nnp[(size_t)gr*4 + 3];
    unsigned long long pm = min(min(p0, p1), min(p2, p3));
    int nn = (int)(pm & 0xffffffffu);
    float ga = gaps[gr*REPC + 0], gb = gaps[gr*REPC + 1];
    int ra = NV + 2*gr, rb = ra + 1;
    #pragma unroll
    for (int u = 0; u < 16; u += 4) {
        float4 cv = *(const float4*)&g_x[(size_t)gr*HH + c0 + u];
        float4 nv = *(const float4*)&g_x[(size_t)nn*HH + c0 + u];
        float4 oa, ob;
        oa.x = cv.x + ga*(nv.x - cv.x); oa.y = cv.y + ga*(nv.y - cv.y);
        oa.z = cv.z + ga*(nv.z - cv.z); oa.w = cv.w + ga*(nv.w - cv.w);
        ob.x = cv.x + gb*(nv.x - cv.x); ob.y = cv.y + gb*(nv.y - cv.y);
        ob.z = cv.z + gb*(nv.z - cv.z); ob.w = cv.w + gb*(nv.w - cv.w);
        *(float4*)&g_x[(size_t)ra*HH + c0 + u] = oa;
        *(float4*)&g_x[(size_t)rb*HH + c0 + u] = ob;
        int h = c0 + u;
        g_xt[(size_t)(h+0)*XR + ra] = tf32r(oa.x);
        g_xt[(size_t)(h+1)*XR + ra] = tf32r(oa.y);
        g_xt[(size_t)(h+2)*XR + ra] = tf32r(oa.z);
        g_xt[(size_t)(h+3)*XR + ra] = tf32r(oa.w);
        g_xt[(size_t)(h+0)*XR + rb] = tf32r(ob.x);
        g_xt[(size_t)(h+1)*XR + rb] = tf32r(ob.y);
        g_xt[(size_t)(h+2)*XR + rb] = tf32r(ob.z);
        g_xt[(size_t)(h+3)*XR + rb] = tf32r(ob.w);
    }
}

// ---------------- fused tf32-MMA (round-9 proven config) --------------------
__global__ void __launch_bounds__(256, 2) k_fused5(const float* __restrict__ adj) {
    extern __shared__ float dsm[];
    float* soi = dsm;                    // [64][132] out_i
    float* buf = dsm + 64*132;           // union: out_j [64][132] / xT [128][68]
    float* sp  = buf + 128*68;           // [64][68] thresholded P (tf32)
    float* srs = sp + 64*68;             // [2][64] rowsum partials
    float* lred = srs + 128;             // [3][8] cnt / S_non / S_edge

    int t    = threadIdx.x;
    int lane = t & 31, warp = t >> 5;
    int wi = warp >> 1, wj = warp & 1;
    int g  = lane >> 2, c = lane & 3;
    int i0 = blockIdx.x * 64;
    int chunk = blockIdx.y;
    int jbase = chunk * CHJ;
    bool lossi = (i0 < NV) && (chunk < 2);
    unsigned bufb = (unsigned)__cvta_generic_to_shared(buf);

    {
        const float4* src = (const float4*)&g_out[(size_t)i0*HH];
        unsigned soib = (unsigned)__cvta_generic_to_shared(soi);
        for (int l = t; l < 2048; l += 256) {
            int r = l >> 5, kq = l & 31;
            cpa16(soib + (unsigned)(r*33 + kq)*16u, src + l);
        }
    }

    float nacc[8][4];
    #pragma unroll
    for (int nt = 0; nt < 8; nt++)
        #pragma unroll
        for (int q = 0; q < 4; q++) nacc[nt][q] = 0.f;
    float rsum0 = 0.f, rsum1 = 0.f;
    float lcnt = 0.f, lsnon = 0.f, lsedge = 0.f;

    const float* Ab = soi + (wi*16)*132;
    const float* Pb = sp  + (wi*16)*68;

    for (int jt = 0; jt < CHJ/64; jt++) {
        int j0 = jbase + jt*64;
        __syncthreads();   // protect buf from previous neigh readers
        {
            const float4* src = (const float4*)&g_out[(size_t)j0*HH];
            for (int l = t; l < 2048; l += 256) {
                int r = l >> 5, kq = l & 31;
                cpa16(bufb + (unsigned)(r*33 + kq)*16u, src + l);
            }
            cpa_commit_wait();
        }
        __syncthreads();

        // ---- gram MMA ----
        float dg[4][4];
        #pragma unroll
        for (int nt = 0; nt < 4; nt++)
            #pragma unroll
            for (int q = 0; q < 4; q++) dg[nt][q] = 0.f;
        const float* Bb = buf + (wj*32)*132;
        #pragma unroll 4
        for (int ks = 0; ks < 16; ks++) {
            int k = ks*8;
            unsigned a0 = __float_as_uint(Ab[(g    )*132 + k + c    ]);
            unsigned a1 = __float_as_uint(Ab[(g + 8)*132 + k + c    ]);
            unsigned a2 = __float_as_uint(Ab[(g    )*132 + k + c + 4]);
            unsigned a3 = __float_as_uint(Ab[(g + 8)*132 + k + c + 4]);
            #pragma unroll
            for (int nt = 0; nt < 4; nt++) {
                unsigned b0 = __float_as_uint(Bb[(nt*8 + g)*132 + k + c    ]);
                unsigned b1 = __float_as_uint(Bb[(nt*8 + g)*132 + k + c + 4]);
                mma8(dg[nt], a0, a1, a2, a3, b0, b1);
            }
        }

        // ---- epilogue: sigmoid, split loss, rowsum, write P ----
        #pragma unroll
        for (int nt = 0; nt < 4; nt++) {
            int lj = wj*32 + nt*8 + c*2;
            int gj = j0 + lj;
            int r0 = i0 + wi*16 + g, r1 = r0 + 8;
            float p0 = 1.f/(1.f + __expf(-dg[nt][0]));
            float p1 = 1.f/(1.f + __expf(-dg[nt][1]));
            float p2 = 1.f/(1.f + __expf(-dg[nt][2]));
            float p3 = 1.f/(1.f + __expf(-dg[nt][3]));
            if (lossi) {
                float2 a0v = *(const float2*)&adj[(size_t)r0*NV + gj];
                float2 a1v = *(const float2*)&adj[(size_t)r1*NV + gj];
                float e0 = p0 - a0v.x, e1 = p1 - a0v.y;
                float e2 = p2 - a1v.x, e3 = p3 - a1v.y;
                float q0 = e0*e0, q1 = e1*e1, q2 = e2*e2, q3 = e3*e3;
                bool z0 = (a0v.x == 0.f), z1 = (a0v.y == 0.f);
                bool z2 = (a1v.x == 0.f), z3 = (a1v.y == 0.f);
                lcnt   += (z0?0.f:1.f) + (z1?0.f:1.f) + (z2?0.f:1.f) + (z3?0.f:1.f);
                lsnon  += (z0?q0:0.f) + (z1?q1:0.f) + (z2?q2:0.f) + (z3?q3:0.f);
                lsedge += (z0?0.f:q0) + (z1?0.f:q1) + (z2?0.f:q2) + (z3?0.f:q3);
            }
            float t0 = (p0 >= 0.5f) ? p0 : 0.f;
            float t1 = (p1 >= 0.5f) ? p1 : 0.f;
            float t2 = (p2 >= 0.5f) ? p2 : 0.f;
            float t3 = (p3 >= 0.5f) ? p3 : 0.f;
            rsum0 += t0 + t1;  rsum1 += t2 + t3;
            *(float2*)&sp[(wi*16 + g    )*68 + lj] = make_float2(tf32r(t0), tf32r(t1));
            *(float2*)&sp[(wi*16 + g + 8)*68 + lj] = make_float2(tf32r(t2), tf32r(t3));
        }
        __syncthreads();   // sp complete; buf free

        {
            const float* srcb = g_xt + j0;
            for (int l = t; l < 2048; l += 256) {
                int h = l >> 4, q = l & 15;
                cpa16(bufb + (unsigned)(h*17 + q)*16u, &srcb[(size_t)h*XR + q*4]);
            }
            cpa_commit_wait();
        }
        __syncthreads();

        // ---- neigh MMA ----
        #pragma unroll 2
        for (int ks = 0; ks < 8; ks++) {
            int k = ks*8;
            unsigned a0 = __float_as_uint(Pb[(g    )*68 + k + c    ]);
            unsigned a1 = __float_as_uint(Pb[(g + 8)*68 + k + c    ]);
            unsigned a2 = __float_as_uint(Pb[(g    )*68 + k + c + 4]);
            unsigned a3 = __float_as_uint(Pb[(g + 8)*68 + k + c + 4]);
            #pragma unroll
            for (int nt = 0; nt < 8; nt++) {
                unsigned b0 = __float_as_uint(buf[(wj*64 + nt*8 + g)*68 + k + c    ]);
                unsigned b1 = __float_as_uint(buf[(wj*64 + nt*8 + g)*68 + k + c + 4]);
                mma8(nacc[nt], a0, a1, a2, a3, b0, b1);
            }
        }
    }

    // ---- write neigh partials (exclusive per chunk) ----
    size_t cb = (size_t)chunk * XR;
    #pragma unroll
    for (int nt = 0; nt < 8; nt++) {
        int h = wj*64 + nt*8 + c*2;
        int r0 = i0 + wi*16 + g, r1 = r0 + 8;
        *(float2*)&g_ng4[(cb + r0)*HH + h] = make_float2(nacc[nt][0], nacc[nt][1]);
        *(float2*)&g_ng4[(cb + r1)*HH + h] = make_float2(nacc[nt][2], nacc[nt][3]);
    }

    // ---- rowsums ----
    #pragma unroll
    for (int o = 1; o <= 2; o <<= 1) {
        rsum0 += __shfl_xor_sync(0xffffffffu, rsum0, o);
        rsum1 += __shfl_xor_sync(0xffffffffu, rsum1, o);
    }
    if (c == 0) {
        srs[wj*64 + wi*16 + g    ] = rsum0;
        srs[wj*64 + wi*16 + g + 8] = rsum1;
    }
    // ---- count + split-loss reduction ----
    #pragma unroll
    for (int o = 16; o; o >>= 1) {
        lcnt   += __shfl_down_sync(0xffffffffu, lcnt,   o);
        lsnon  += __shfl_down_sync(0xffffffffu, lsnon,  o);
        lsedge += __shfl_down_sync(0xffffffffu, lsedge, o);
    }
    if (lane == 0) {
        lred[warp]      = lcnt;
        lred[8 + warp]  = lsnon;
        lred[16 + warp] = lsedge;
    }
    __syncthreads();
    if (t < 64) g_rs4[cb + i0 + t] = srs[t] + srs[64 + t];
    if (t == 0 && lossi) {
        float sc = 0.f, sn = 0.f, se = 0.f;
        for (int q = 0; q < 8; q++) { sc += lred[q]; sn += lred[8+q]; se += lred[16+q]; }
        atomicAdd(&g_scal[0], sc);
        atomicAdd(&g_scal[2], sn);
        atomicAdd(&g_scal[3], se);
    }
}

// ---------------- merged classifier: weff + logits + y + loss ---------------
__global__ void __launch_bounds__(256) k_final2(
    const float* __restrict__ Wclf, const float* __restrict__ Wconv,
    const float* __restrict__ bclf, const int* __restrict__ labels,
    float* __restrict__ ob)
{
    __shared__ float sw[512];
    int t = threadIdx.x, lane = t & 31, warp = t >> 5;
    for (int idx = t; idx < 512; idx += 256) {
        int cc = idx >> 8, k = idx & 255;
        float s = 0.f;
        for (int o = 0; o < HH; o++) s += Wclf[cc*HH + o] * Wconv[o*256 + k];
        sw[idx] = s;
    }
    __syncthreads();
    int i0 = blockIdx.x*32;
    float b0 = bclf[0], b1 = bclf[1];
    #pragma unroll
    for (int q = 0; q < 4; q++) {
        int w = i0 + warp*4 + q;
        float rs = g_rs4[w] + g_rs4[XR + w] + g_rs4[2*XR + w];
        float inv = 1.f / (rs + 1.f);
        float l0 = 0.f, l1 = 0.f;
        for (int k = lane; k < HH; k += 32) {
            float xv = g_x[(size_t)w*HH + k];
            float nv = (g_ng4[(size_t)w*HH + k] + g_ng4[((size_t)XR + w)*HH + k]
                      + g_ng4[((size_t)2*XR + w)*HH + k]) * inv;
            l0 += xv*sw[k]       + nv*sw[128 + k];
            l1 += xv*sw[256 + k] + nv*sw[256 + 128 + k];
        }
        #pragma unroll
        for (int o = 16; o; o >>= 1) {
            l0 += __shfl_down_sync(0xffffffffu, l0, o);
            l1 += __shfl_down_sync(0xffffffffu, l1, o);
        }
        if (lane == 0) {
            ob[w*2 + 0] = l0 + b0;
            ob[w*2 + 1] = l1 + b1;
        }
    }
    if (t < 32) {
        int gr = i0 + t;
        ob[XR*2 + gr] = (gr < NV) ? (float)labels[gr] : 1.f;
    }
    if (blockIdx.x == 0 && t == 0) {
        float e = g_scal[0];
        float negw = e / (16777216.f - e);
        ob[XR*2 + XR] = g_scal[3] + negw * g_scal[2];
    }
}

// ---------------- launcher --------------------------------------------------
extern "C" void kernel_launch(void* const* d_in, const int* in_sizes, int n_in,
                              void* d_out, int out_size) {
    const float* feat     = (const float*)d_in[0];
    const float* adj      = (const float*)d_in[1];
    const int*   src      = (const int*)  d_in[2];
    const int*   dst      = (const int*)  d_in[3];
    const int*   labels   = (const int*)  d_in[4];
    const float* W_pool0  = (const float*)d_in[5];
    const float* b_pool0  = (const float*)d_in[6];
    const float* W_self0  = (const float*)d_in[7];
    const float* W_neigh0 = (const float*)d_in[8];
    const float* b0       = (const float*)d_in[9];
    const float* W_pool1  = (const float*)d_in[10];
    const float* b_pool1  = (const float*)d_in[11];
    const float* W_self1  = (const float*)d_in[12];
    const float* W_neigh1 = (const float*)d_in[13];
    const float* b1       = (const float*)d_in[14];
    const float* de_w     = (const float*)d_in[15];
    const float* W_conv   = (const float*)d_in[16];
    const float* W_clf    = (const float*)d_in[17];
    const float* b_clf    = (const float*)d_in[18];
    const float* gaps     = (const float*)d_in[19];
    int E = in_sizes[2];
    float* ob = (float*)d_out;

    float *p0, *hn0, *hh, *p1, *hn1, *xv, *ov;
    cudaGetSymbolAddress((void**)&p0,  g_p0);
    cudaGetSymbolAddress((void**)&hn0, g_hn0);
    cudaGetSymbolAddress((void**)&hh,  g_h);
    cudaGetSymbolAddress((void**)&p1,  g_p1);
    cudaGetSymbolAddress((void**)&hn1, g_hn1);
    cudaGetSymbolAddress((void**)&xv,  g_x);
    cudaGetSymbolAddress((void**)&ov,  g_out);

    const int FUSED_SMEM = (64*132 + 128*68 + 64*68 + 128 + 24) * 4;  // 86624 B
    const int TGEMM_SMEM = 4*64*68*4;                                 // 69632 B
    cudaFuncSetAttribute(k_fused5, cudaFuncAttributeMaxDynamicSharedMemorySize, FUSED_SMEM);
    cudaFuncSetAttribute(k_tgemm,  cudaFuncAttributeMaxDynamicSharedMemorySize, TGEMM_SMEM);

    k_init<<<(NV+255)/256, 256>>>();
    k_build<<<(E+255)/256, 256>>>(src, dst, E);

    // layer 0
    k_tgemm<<<dim3(FIN/64, NV/64), 256, TGEMM_SMEM>>>(feat, W_pool0, FIN,
        (const float*)0, (const float*)0, 0, b_pool0, p0, FIN, 1, 0, 0);
    k_gmax4<<<NV/4, 256>>>(p0, hn0, FIN);
    k_tgemm<<<dim3(HH/64, NV/64), 256, TGEMM_SMEM>>>(feat, W_self0, FIN, hn0, W_neigh0, FIN,
        b0, hh, HH, 0, 0, 0);
    k_relu_l2norm<<<NV, HH>>>(hh);

    // layer 1
    k_tgemm<<<dim3(HH/64, NV/64), 256, TGEMM_SMEM>>>(hh, W_pool1, HH,
        (const float*)0, (const float*)0, 0, b_pool1, p1, HH, 1, 0, 0);
    k_gmax4<<<NV/8, 256>>>(p1, hn1, HH);
    k_tgemm<<<dim3(HH/64, NV/64), 256, TGEMM_SMEM>>>(hh, W_self1, HH, hn1, W_neigh1, HH,
        b1, xv, HH, 0, 0, 1);   // also writes g_xt rows < NV

    // SMOTE (4-way parallel NN + interp writing synth rows + g_xt)
    k_smote_nn<<<dim3(MINC/32, 4), 256>>>();
    k_smote_int<<<MINC/32, 256>>>(gaps);

    // decoder input (3xTF32, tf32-rounded epilogue feeds fused pass directly)
    k_tgemm<<<dim3(HH/64, XR/64), 256, TGEMM_SMEM>>>(xv, de_w, HH,
        (const float*)0, (const float*)0, 0, (const float*)0, ov, HH, 0, 1, 0);

    // big fused pass (tensor cores; 64-row tiles, 2 blocks/SM)
    k_fused5<<<dim3(XR/64, NCH), 256, FUSED_SMEM>>>(adj);

    // merged classifier + y + loss
    k_final2<<<XR/32, 256>>>(W_clf, W_conv, b_clf, labels, ob);
}